// round 4
// baseline (speedup 1.0000x reference)
#include <cuda_runtime.h>

#define BB 8
#define NN 2048
#define DD 1024
#define TT 5            // Taylor terms
#define CC 64           // chunks along N
#define LL 32           // NN / CC
#define DSPLIT 2
#define DHALF (DD / DSPLIT)          // 512 floats per CTA d-slice
#define NT 128                       // threads per CTA (DHALF/4)
#define ENTRY (TT * DHALF + 16)      // floats per chain entry (pad keeps 16B align)
#define NCHAIN (BB * DSPLIT)         // 16 chains

// Scratch (static device arrays; no cudaMalloc allowed)
__device__ float g_k[BB * NN];
__device__ float g_q[BB * NN];
__device__ float g_agg [(size_t)NCHAIN * CC * ENTRY];
__device__ float g_pref[(size_t)NCHAIN * CC * ENTRY];
__device__ volatile int g_flag[NCHAIN * CC];   // 0=none 1=aggregate 2=inclusive prefix

// ---------------------------------------------------------------------------
// K1: k[b,i] = x[b,i,:]·wk, q[b,i] = x[b,i,:]·wq. One warp per row.
// Block 0 also resets the lookback flags for this launch.
// ---------------------------------------------------------------------------
__global__ __launch_bounds__(256) void k_proj(const float* __restrict__ x,
                                              const float* __restrict__ wk,
                                              const float* __restrict__ wq) {
    if (blockIdx.x == 0) {
        for (int i = threadIdx.x; i < NCHAIN * CC; i += 256)
            *(int*)&g_flag[i] = 0;
    }
    int warp = threadIdx.x >> 5;
    int lane = threadIdx.x & 31;
    int row  = blockIdx.x * 8 + warp;            // [0, BB*NN)
    const float4* xr  = reinterpret_cast<const float4*>(x) + (size_t)row * (DD / 4);
    const float4* wk4 = reinterpret_cast<const float4*>(wk);
    const float4* wq4 = reinterpret_cast<const float4*>(wq);
    float sk = 0.f, sq = 0.f;
#pragma unroll
    for (int i = lane; i < DD / 4; i += 32) {
        float4 v = xr[i];
        float4 a = wk4[i];
        float4 b = wq4[i];
        sk += v.x * a.x + v.y * a.y + v.z * a.z + v.w * a.w;
        sq += v.x * b.x + v.y * b.y + v.z * b.z + v.w * b.w;
    }
#pragma unroll
    for (int off = 16; off > 0; off >>= 1) {
        sk += __shfl_down_sync(0xffffffffu, sk, off);
        sq += __shfl_down_sync(0xffffffffu, sq, off);
    }
    if (lane == 0) {
        g_k[row] = sk;
        g_q[row] = sq;
    }
}

// ---------------------------------------------------------------------------
// K2 (fused): per-chunk moment aggregate + decoupled-lookback scan + output.
// Grid (DSPLIT, CC, BB), 128 threads. Chain = (b, dsplit); position = ch.
// Entry layout: TT rows of DHALF floats (vector moments for this d-slice),
// then TT scalar moments at offset TT*DHALF.
// ---------------------------------------------------------------------------
__global__ __launch_bounds__(NT) void k_fused(const float* __restrict__ f,
                                              float* __restrict__ out) {
    const int ds    = blockIdx.x;
    const int ch    = blockIdx.y;
    const int b     = blockIdx.z;
    const int tid   = threadIdx.x;
    const int chain = b * DSPLIT + ds;

    __shared__ float sk[LL], sq[LL], sP[TT];
    __shared__ int sflag;
    if (tid < LL) {
        sk[tid] = g_k[b * NN + ch * LL + tid];
        sq[tid] = g_q[b * NN + ch * LL + tid];
    }
    __syncthreads();

    const float4* fp = reinterpret_cast<const float4*>(
        f + (size_t)(b * NN + ch * LL) * DD + (size_t)ds * DHALF) + tid;

    // ---- phase 1: local vector aggregate S_t = sum_j k_j^t f_j ----
    float4 S[TT];
#pragma unroll
    for (int t = 0; t < TT; t++) S[t] = make_float4(0.f, 0.f, 0.f, 0.f);
#pragma unroll 8
    for (int j = 0; j < LL; j++) {
        float4 fv = fp[(size_t)j * (DD / 4)];
        float kj = sk[j];
        S[0].x += fv.x; S[0].y += fv.y; S[0].z += fv.z; S[0].w += fv.w;
        float pk = kj;
#pragma unroll
        for (int t = 1; t < TT; t++) {
            S[t].x += pk * fv.x; S[t].y += pk * fv.y;
            S[t].z += pk * fv.z; S[t].w += pk * fv.w;
            pk *= kj;
        }
    }

    // scalar aggregate (thread 0 only needs it)
    float As[TT];
#pragma unroll
    for (int t = 0; t < TT; t++) As[t] = 0.f;
    if (tid == 0) {
#pragma unroll
        for (int j = 0; j < LL; j++) {
            float p = 1.f, kj = sk[j];
#pragma unroll
            for (int t = 0; t < TT; t++) { As[t] += p; p *= kj; }
        }
    }

    const size_t my = (size_t)(chain * CC + ch) * ENTRY;

    // E = exclusive prefix (vector), Es = exclusive prefix (scalar, tid0)
    float4 E[TT];
#pragma unroll
    for (int t = 0; t < TT; t++) E[t] = make_float4(0.f, 0.f, 0.f, 0.f);
    float Es[TT];
#pragma unroll
    for (int t = 0; t < TT; t++) Es[t] = 0.f;

    if (ch == 0) {
        // prefix == aggregate; publish directly as prefix
        float4* dst = reinterpret_cast<float4*>(g_pref + my);
#pragma unroll
        for (int t = 0; t < TT; t++) dst[t * (DHALF / 4) + tid] = S[t];
        if (tid == 0) {
#pragma unroll
            for (int t = 0; t < TT; t++) g_pref[my + TT * DHALF + t] = As[t];
        }
        __threadfence();
        __syncthreads();
        if (tid == 0) {
            g_flag[chain * CC] = 2;
#pragma unroll
            for (int t = 0; t < TT; t++) sP[t] = 0.f;
        }
        __syncthreads();
    } else {
        // publish aggregate
        {
            float4* dst = reinterpret_cast<float4*>(g_agg + my);
#pragma unroll
            for (int t = 0; t < TT; t++) dst[t * (DHALF / 4) + tid] = S[t];
            if (tid == 0) {
#pragma unroll
                for (int t = 0; t < TT; t++) g_agg[my + TT * DHALF + t] = As[t];
            }
        }
        __threadfence();
        __syncthreads();
        if (tid == 0) g_flag[chain * CC + ch] = 1;

        // ---- lookback ----
        int i = ch - 1;
        while (true) {
            if (tid == 0) {
                int fl;
                do { fl = g_flag[chain * CC + i]; } while (fl == 0);
                sflag = fl;
            }
            __syncthreads();
            const int fl = sflag;
            const float* src = (fl == 2 ? g_pref : g_agg) +
                               (size_t)(chain * CC + i) * ENTRY;
            const float4* s4 = reinterpret_cast<const float4*>(src);
#pragma unroll
            for (int t = 0; t < TT; t++) {
                float4 v = s4[t * (DHALF / 4) + tid];
                E[t].x += v.x; E[t].y += v.y; E[t].z += v.z; E[t].w += v.w;
            }
            if (tid == 0) {
#pragma unroll
                for (int t = 0; t < TT; t++) Es[t] += src[TT * DHALF + t];
            }
            __syncthreads();            // protect sflag before next iteration
            if (fl == 2) break;
            i--;
        }

        // publish inclusive prefix (not needed for the last chunk)
        if (ch < CC - 1) {
            float4* dstp = reinterpret_cast<float4*>(g_pref + my);
#pragma unroll
            for (int t = 0; t < TT; t++) {
                float4 v;
                v.x = E[t].x + S[t].x; v.y = E[t].y + S[t].y;
                v.z = E[t].z + S[t].z; v.w = E[t].w + S[t].w;
                dstp[t * (DHALF / 4) + tid] = v;
            }
            if (tid == 0) {
#pragma unroll
                for (int t = 0; t < TT; t++)
                    g_pref[my + TT * DHALF + t] = Es[t] + As[t];
            }
            __threadfence();
            __syncthreads();
            if (tid == 0) g_flag[chain * CC + ch] = 2;
        }
        if (tid == 0) {
#pragma unroll
            for (int t = 0; t < TT; t++) sP[t] = Es[t];
        }
        __syncthreads();
    }

    // ---- phase 2: replay rows, emit output ----
    float P[TT];
#pragma unroll
    for (int t = 0; t < TT; t++) P[t] = sP[t];   // exclusive scalar prefix

    float4* op = reinterpret_cast<float4*>(
        out + (size_t)(b * NN + ch * LL) * DD + (size_t)ds * DHALF) + tid;

#pragma unroll 4
    for (int j = 0; j < LL; j++) {
        float4 fv = fp[(size_t)j * (DD / 4)];    // L1/L2 hit (phase-1 re-read)
        float kj = sk[j];
        // running inclusive sums (include i = j)
        E[0].x += fv.x; E[0].y += fv.y; E[0].z += fv.z; E[0].w += fv.w;
        P[0] += 1.f;
        float pk = kj;
#pragma unroll
        for (int t = 1; t < TT; t++) {
            E[t].x += pk * fv.x; E[t].y += pk * fv.y;
            E[t].z += pk * fv.z; E[t].w += pk * fv.w;
            P[t] += pk;
            pk *= kj;
        }
        // Taylor coefficients of exp(c*k): c^t / t!
        float c   = sq[j] * 0.03125f;            // q_j / sqrt(D)
        float co1 = c;
        float co2 = c * c * 0.5f;
        float co3 = co2 * c * (1.f / 3.f);
        float co4 = co3 * c * 0.25f;
        float Z = P[0] + co1 * P[1] + co2 * P[2] + co3 * P[3] + co4 * P[4];
        float iz = 1.f / Z;
        float4 acc;
        acc.x = E[0].x + co1 * E[1].x + co2 * E[2].x + co3 * E[3].x + co4 * E[4].x;
        acc.y = E[0].y + co1 * E[1].y + co2 * E[2].y + co3 * E[3].y + co4 * E[4].y;
        acc.z = E[0].z + co1 * E[1].z + co2 * E[2].z + co3 * E[3].z + co4 * E[4].z;
        acc.w = E[0].w + co1 * E[1].w + co2 * E[2].w + co3 * E[3].w + co4 * E[4].w;
        acc.x *= iz; acc.y *= iz; acc.z *= iz; acc.w *= iz;
        op[(size_t)j * (DD / 4)] = acc;
    }
}

// ---------------------------------------------------------------------------
extern "C" void kernel_launch(void* const* d_in, const int* in_sizes, int n_in,
                              void* d_out, int out_size) {
    const float* x  = (const float*)d_in[0];
    const float* f  = (const float*)d_in[1];
    const float* wk = (const float*)d_in[2];
    const float* wq = (const float*)d_in[3];
    float* out = (float*)d_out;

    k_proj<<<BB * NN / 8, 256>>>(x, wk, wq);
    dim3 g(DSPLIT, CC, BB);                  // (2, 64, 8) = 1024 CTAs
    k_fused<<<g, NT>>>(f, out);
}

// round 5
// speedup vs baseline: 1.2560x; 1.2560x over previous
#include <cuda_runtime.h>

#define BB 8
#define NN 2048
#define DD 1024
#define TT 5     // Taylor terms (|c*k| <= ~0.18 -> term-5 trunc ~1.6e-6 rel)
#define CC 64    // chunks along N
#define LL 32    // NN / CC

// Scratch (static device arrays; no cudaMalloc allowed)
__device__ float g_k[BB * NN];
__device__ float g_q[BB * NN];
__device__ float g_coef[BB * NN * TT];           // per-(b,j): c^t/t! * invZ
__device__ float g_part[BB * CC * TT * DD];      // chunk moment partials -> exclusive prefixes

// ---------------------------------------------------------------------------
// K1: k[b,i] = x[b,i,:]·wk, q[b,i] = x[b,i,:]·wq. One warp per row.
// ---------------------------------------------------------------------------
__global__ __launch_bounds__(256) void k_proj(const float* __restrict__ x,
                                              const float* __restrict__ wk,
                                              const float* __restrict__ wq) {
    int warp = threadIdx.x >> 5;
    int lane = threadIdx.x & 31;
    int row  = blockIdx.x * 8 + warp;            // [0, BB*NN)
    const float4* xr  = reinterpret_cast<const float4*>(x) + (size_t)row * (DD / 4);
    const float4* wk4 = reinterpret_cast<const float4*>(wk);
    const float4* wq4 = reinterpret_cast<const float4*>(wq);
    float sk = 0.f, sq = 0.f;
#pragma unroll
    for (int i = lane; i < DD / 4; i += 32) {
        float4 v = xr[i];
        float4 a = wk4[i];
        float4 b = wq4[i];
        sk += v.x * a.x + v.y * a.y + v.z * a.z + v.w * a.w;
        sq += v.x * b.x + v.y * b.y + v.z * b.z + v.w * b.w;
    }
#pragma unroll
    for (int off = 16; off > 0; off >>= 1) {
        sk += __shfl_down_sync(0xffffffffu, sk, off);
        sq += __shfl_down_sync(0xffffffffu, sq, off);
    }
    if (lane == 0) {
        g_k[row] = sk;
        g_q[row] = sq;
    }
}

// ---------------------------------------------------------------------------
// K2: per (b, chunk, d-slice) accumulate chunk moment partials S_t = sum k^t f
// 256 threads, float2 per thread (same traffic as float4x128, 2x occupancy).
// Grid (2, CC, BB).
// ---------------------------------------------------------------------------
__global__ __launch_bounds__(256) void k_part(const float* __restrict__ f) {
    int b  = blockIdx.z;
    int ch = blockIdx.y;
    int d2 = blockIdx.x * 256 + threadIdx.x;          // [0, DD/2)

    __shared__ float sk[LL];
    if (threadIdx.x < LL) sk[threadIdx.x] = g_k[b * NN + ch * LL + threadIdx.x];
    __syncthreads();

    const float2* fp = reinterpret_cast<const float2*>(
        f + (size_t)(b * NN + ch * LL) * DD) + d2;

    float2 S[TT];
#pragma unroll
    for (int t = 0; t < TT; t++) S[t] = make_float2(0.f, 0.f);

#pragma unroll 8
    for (int j = 0; j < LL; j++) {
        float2 fv = fp[(size_t)j * (DD / 2)];
        float kj = sk[j];
        S[0].x += fv.x; S[0].y += fv.y;
        float pk = kj;
#pragma unroll
        for (int t = 1; t < TT; t++) {
            S[t].x += pk * fv.x; S[t].y += pk * fv.y;
            pk *= kj;
        }
    }

    float2* gp = reinterpret_cast<float2*>(
        g_part + (size_t)((b * CC + ch) * TT) * DD) + d2;
#pragma unroll
    for (int t = 0; t < TT; t++) gp[(size_t)t * (DD / 2)] = S[t];
}

// ---------------------------------------------------------------------------
// K3 (fused): blocks [0, SCAN_BLOCKS) do the cross-chunk exclusive scan of
// g_part; blocks [SCAN_BLOCKS, SCAN_BLOCKS+BB) compute per-(b,j) Taylor
// coefficients (scalar moment scan + 1/Z fold).
// ---------------------------------------------------------------------------
#define SCAN_BLOCKS ((BB * TT * DD) / 256)   // 160

__global__ __launch_bounds__(256) void k_mid() {
    int tid = threadIdx.x;

    if (blockIdx.x < SCAN_BLOCKS) {
        // ---- cross-chunk exclusive scan, register-blocked in two halves ----
        int idx = blockIdx.x * 256 + tid;            // [0, BB*TT*DD)
        int d   = idx % DD;
        int t   = (idx / DD) % TT;
        int b   = idx / (DD * TT);

        size_t base   = (size_t)((b * CC) * TT + t) * DD + d;
        size_t stride = (size_t)TT * DD;

        float run = 0.f;
#pragma unroll
        for (int half = 0; half < 2; half++) {
            float v[CC / 2];
#pragma unroll
            for (int c = 0; c < CC / 2; c++)
                v[c] = g_part[base + (half * (CC / 2) + c) * stride];
#pragma unroll
            for (int c = 0; c < CC / 2; c++) {
                float tmp = v[c];
                v[c] = run;
                run += tmp;
            }
#pragma unroll
            for (int c = 0; c < CC / 2; c++)
                g_part[base + (half * (CC / 2) + c) * stride] = v[c];
        }
        return;
    }

    // ---- per-batch scalar moment scan + coefficient fold ----
    int b  = blockIdx.x - SCAN_BLOCKS;
    int j0 = b * NN + tid * 8;

    float kv[8];
#pragma unroll
    for (int r = 0; r < 8; r++) kv[r] = g_k[j0 + r];

    float seg[TT];
#pragma unroll
    for (int t = 0; t < TT; t++) seg[t] = 0.f;
#pragma unroll
    for (int r = 0; r < 8; r++) {
        float p = 1.f;
#pragma unroll
        for (int t = 0; t < TT; t++) { seg[t] += p; p *= kv[r]; }
    }

    __shared__ float sh[TT * 256];
    float run[TT];
#pragma unroll
    for (int t = 0; t < TT; t++) run[t] = seg[t];
    for (int off = 1; off < 256; off <<= 1) {
#pragma unroll
        for (int t = 0; t < TT; t++) sh[t * 256 + tid] = run[t];
        __syncthreads();
        if (tid >= off) {
#pragma unroll
            for (int t = 0; t < TT; t++) run[t] += sh[t * 256 + tid - off];
        }
        __syncthreads();
    }

    float P[TT];
#pragma unroll
    for (int t = 0; t < TT; t++) P[t] = run[t] - seg[t];   // exclusive prefix

    const float invfact[TT] = {1.f, 1.f, 0.5f, 1.f / 6.f, 1.f / 24.f};
#pragma unroll
    for (int r = 0; r < 8; r++) {
        float p = 1.f;
#pragma unroll
        for (int t = 0; t < TT; t++) { P[t] += p; p *= kv[r]; }   // include i=j
        float c  = g_q[j0 + r] * 0.03125f;                        // q_j / sqrt(D)
        float pw = 1.f, Z = 0.f;
        float co[TT];
#pragma unroll
        for (int t = 0; t < TT; t++) {
            co[t] = pw * invfact[t];
            Z    += co[t] * P[t];
            pw   *= c;
        }
        float iz = 1.f / Z;
#pragma unroll
        for (int t = 0; t < TT; t++) g_coef[(size_t)(j0 + r) * TT + t] = co[t] * iz;
    }
}

// ---------------------------------------------------------------------------
// K4: resume the scan within each chunk and emit output:
// out[b,j,d] = sum_t coef[b,j,t] * S_t(j,d)
// 256 threads, float2 per thread. Grid (2, CC, BB).
// ---------------------------------------------------------------------------
__global__ __launch_bounds__(256) void k_out(const float* __restrict__ f,
                                             float* __restrict__ out) {
    int b   = blockIdx.z;
    int ch  = blockIdx.y;
    int tid = threadIdx.x;
    int d2  = blockIdx.x * 256 + tid;

    __shared__ float sk[LL];
    __shared__ float sco[LL * TT];
    int jbase = b * NN + ch * LL;
    if (tid < LL) sk[tid] = g_k[jbase + tid];
    for (int i = tid; i < LL * TT; i += 256)
        sco[i] = g_coef[(size_t)jbase * TT + i];
    __syncthreads();

    float2 S[TT];
    const float2* gp = reinterpret_cast<const float2*>(
        g_part + (size_t)((b * CC + ch) * TT) * DD) + d2;
#pragma unroll
    for (int t = 0; t < TT; t++) S[t] = gp[(size_t)t * (DD / 2)];

    const float2* fp = reinterpret_cast<const float2*>(f + (size_t)jbase * DD) + d2;
    float2*       op = reinterpret_cast<float2*>(out + (size_t)jbase * DD) + d2;

#pragma unroll 8
    for (int j = 0; j < LL; j++) {
        float2 fv = fp[(size_t)j * (DD / 2)];
        float kj = sk[j];
        S[0].x += fv.x; S[0].y += fv.y;
        float pk = kj;
#pragma unroll
        for (int t = 1; t < TT; t++) {
            S[t].x += pk * fv.x; S[t].y += pk * fv.y;
            pk *= kj;
        }
        float2 acc = make_float2(0.f, 0.f);
#pragma unroll
        for (int t = 0; t < TT; t++) {
            float co = sco[j * TT + t];
            acc.x += co * S[t].x; acc.y += co * S[t].y;
        }
        op[(size_t)j * (DD / 2)] = acc;
    }
}

// ---------------------------------------------------------------------------
extern "C" void kernel_launch(void* const* d_in, const int* in_sizes, int n_in,
                              void* d_out, int out_size) {
    const float* x  = (const float*)d_in[0];
    const float* f  = (const float*)d_in[1];
    const float* wk = (const float*)d_in[2];
    const float* wq = (const float*)d_in[3];
    float* out = (float*)d_out;

    k_proj<<<BB * NN / 8, 256>>>(x, wk, wq);
    dim3 g3(2, CC, BB);                      // (2, 64, 8) = 1024 CTAs x 256 thr
    k_part<<<g3, 256>>>(f);
    k_mid<<<SCAN_BLOCKS + BB, 256>>>();      // scan + coef fused
    k_out<<<g3, 256>>>(f, out);
}